// round 11
// baseline (speedup 1.0000x reference)
#include <cuda_runtime.h>
#include <cstdint>

#define LLEN 2048
#define NB   32
#define TS   200
#define VO   34
#define DIN  512
#define HID  256

// ---------------- device-global scratch (no allocation allowed) ----------------
__device__ float g_keyT[(size_t)NB * LLEN * HID];   // (N, L, Q) 64MB
__device__ float g_valT[(size_t)NB * LLEN * HID];   // (N, L, H) 64MB
__device__ float g_h[2][3][HID * NB];               // ping-pong hidden states, transposed (H, N)
__device__ float g_c[3][HID * NB];                  // cell states, transposed (H, N)
__device__ float g_ctxT[HID * NB];                  // context, transposed (H, N)

// ---------------- key/val precompute: C[r, j] = seqs_row(r) . W_row(j) + b ----------------
// r = n*L + l (65536 rows), j in [0,512): j<256 -> key (Wk), else val (Wv)
__global__ void keyval_kernel(const float* __restrict__ seqs,
                              const float* __restrict__ Wk, const float* __restrict__ bk,
                              const float* __restrict__ Wv, const float* __restrict__ bv)
{
    __shared__ float As[16 * 65];
    __shared__ float Bs[16 * 65];
    int tid = threadIdx.x;
    int r0 = blockIdx.y * 64;
    int j0 = blockIdx.x * 64;
    int ty = tid >> 4, tx = tid & 15;

    float acc[4][4];
#pragma unroll
    for (int u = 0; u < 4; u++)
#pragma unroll
        for (int v = 0; v < 4; v++) acc[u][v] = 0.f;

    int lr = tid >> 2;   // 0..63
    int kq = tid & 3;    // 0..3
    int rg = r0 + lr;
    int an = rg >> 11;          // n = r / 2048
    int al = rg & 2047;         // l = r % 2048
    const float* arow = seqs + ((size_t)al * NB + an) * DIN + kq * 4;
    int jg = j0 + lr;
    const float* brow = (jg < HID) ? (Wk + (size_t)jg * DIN + kq * 4)
                                   : (Wv + (size_t)(jg - HID) * DIN + kq * 4);

    for (int kb = 0; kb < DIN; kb += 16) {
        float4 av  = *(const float4*)(arow + kb);
        float4 bvv = *(const float4*)(brow + kb);
        As[(kq * 4 + 0) * 65 + lr] = av.x;
        As[(kq * 4 + 1) * 65 + lr] = av.y;
        As[(kq * 4 + 2) * 65 + lr] = av.z;
        As[(kq * 4 + 3) * 65 + lr] = av.w;
        Bs[(kq * 4 + 0) * 65 + lr] = bvv.x;
        Bs[(kq * 4 + 1) * 65 + lr] = bvv.y;
        Bs[(kq * 4 + 2) * 65 + lr] = bvv.z;
        Bs[(kq * 4 + 3) * 65 + lr] = bvv.w;
        __syncthreads();
#pragma unroll
        for (int k = 0; k < 16; k++) {
            float a[4], b[4];
#pragma unroll
            for (int u = 0; u < 4; u++) a[u] = As[k * 65 + ty * 4 + u];
#pragma unroll
            for (int v = 0; v < 4; v++) b[v] = Bs[k * 65 + tx * 4 + v];
#pragma unroll
            for (int u = 0; u < 4; u++)
#pragma unroll
                for (int v = 0; v < 4; v++) acc[u][v] += a[u] * b[v];
        }
        __syncthreads();
    }

#pragma unroll
    for (int u = 0; u < 4; u++) {
        int r = r0 + ty * 4 + u;
        int n = r >> 11, l = r & 2047;
#pragma unroll
        for (int v = 0; v < 4; v++) {
            int j = j0 + tx * 4 + v;
            if (j < HID) g_keyT[((size_t)n * LLEN + l) * HID + j] = acc[u][v] + bk[j];
            else         g_valT[((size_t)n * LLEN + l) * HID + (j - HID)] = acc[u][v] + bv[j - HID];
        }
    }
}

// ---------------- init hidden/cell state (transposed broadcast of inith/initc) ----------------
__global__ void init_kernel(const float* __restrict__ inith, const float* __restrict__ initc)
{
    int idx = blockIdx.x * 256 + threadIdx.x;   // 0..8191
    int j = idx >> 5;                            // hidden index
#pragma unroll
    for (int layer = 0; layer < 3; ++layer) {
        g_h[0][layer][idx] = inith[layer * HID + j];
        g_c[layer][idx]    = initc[layer * HID + j];
    }
}

// ---------------- one LSTM cell ----------------
// grid 32 blocks x 256 threads; warp = 32 batch lanes for one hidden index jh.
// input [xa ; (emb if layer0) ; hprev] staged transposed in smem (pad 33).
__global__ void lstm_kernel(const float* __restrict__ Wih, const float* __restrict__ Whh,
                            const float* __restrict__ bih, const float* __restrict__ bhh,
                            const int* __restrict__ label_in, const float* __restrict__ emb,
                            int t, int layer, int pi, int din)
{
    extern __shared__ float xs[];   // (din + HID) rows x 33
    const float* xaT  = (layer == 0) ? g_ctxT : g_h[1 - pi][layer - 1];
    const float* hinT = g_h[pi][layer];
    float* houtT      = g_h[1 - pi][layer];
    float* cT         = g_c[layer];
    int tid = threadIdx.x;

    for (int idx = tid; idx < NB * HID; idx += 256) {       // xa (first 256 input cols)
        int k = idx >> 5, n = idx & 31;
        xs[k * 33 + n] = xaT[idx];
    }
    if (layer == 0) {                                        // embedding gather -> cols 256..511
        for (int idx = tid; idx < NB * HID; idx += 256) {
            int n = idx >> 8, k = idx & 255;
            int lab = label_in[n * TS + t];
            xs[(HID + k) * 33 + n] = emb[(size_t)lab * HID + k];
        }
    }
    for (int idx = tid; idx < NB * HID; idx += 256) {        // hprev -> rows din..din+255
        int k = idx >> 5, n = idx & 31;
        xs[(din + k) * 33 + n] = hinT[idx];
    }
    __syncthreads();

    int lane = tid & 31;                     // batch index
    int jh = blockIdx.x * 8 + (tid >> 5);    // hidden index 0..255
    const float* wi = Wih + (size_t)jh * din;
    const float* wf = Wih + (size_t)(jh + HID) * din;
    const float* wg = Wih + (size_t)(jh + 2 * HID) * din;
    const float* wo = Wih + (size_t)(jh + 3 * HID) * din;
    float ai = bih[jh]           + bhh[jh];
    float af = bih[jh + HID]     + bhh[jh + HID];
    float ag = bih[jh + 2 * HID] + bhh[jh + 2 * HID];
    float ao = bih[jh + 3 * HID] + bhh[jh + 3 * HID];

#pragma unroll 4
    for (int k = 0; k < din; ++k) {
        float x = xs[k * 33 + lane];
        ai += wi[k] * x; af += wf[k] * x; ag += wg[k] * x; ao += wo[k] * x;
    }
    const float* vi = Whh + (size_t)jh * HID;
    const float* vf = Whh + (size_t)(jh + HID) * HID;
    const float* vg = Whh + (size_t)(jh + 2 * HID) * HID;
    const float* vo = Whh + (size_t)(jh + 3 * HID) * HID;
#pragma unroll 4
    for (int k = 0; k < HID; ++k) {
        float x = xs[(din + k) * 33 + lane];
        ai += vi[k] * x; af += vf[k] * x; ag += vg[k] * x; ao += vo[k] * x;
    }

    float si = 1.f / (1.f + expf(-ai));
    float sf = 1.f / (1.f + expf(-af));
    float so = 1.f / (1.f + expf(-ao));
    float tg = tanhf(ag);
    int ci = jh * NB + lane;
    float cn = sf * cT[ci] + si * tg;
    cT[ci] = cn;
    houtT[ci] = so * tanhf(cn);
}

// ---------------- fused per-batch tail: q-proj -> scores -> softmax+mask -> ctx -> hid -> logits ----------------
// one block per batch element n, 256 threads
__global__ void attn_kernel(const float* __restrict__ Wq, const float* __restrict__ bq,
                            const int* __restrict__ seq_lens,
                            const float* __restrict__ Wo1, const float* __restrict__ bo1,
                            const float* __restrict__ emb, const float* __restrict__ bo2,
                            float* __restrict__ out, int t, int par)
{
    __shared__ float hs[HID];
    __shared__ float qsm[HID];
    __shared__ float sc[LLEN];
    __shared__ float red[256];
    __shared__ float ctxs[HID];
    __shared__ float hidv[HID];

    int n = blockIdx.x, tid = threadIdx.x;
    const float* h2T = g_h[par][2];

    hs[tid] = h2T[tid * NB + n];
    __syncthreads();

    // q = h2 @ Wq.T + bq
    {
        const float* wr = Wq + (size_t)tid * HID;
        float a = bq[tid];
#pragma unroll 8
        for (int k = 0; k < HID; ++k) a += wr[k] * hs[k];
        qsm[tid] = a;
    }
    __syncthreads();

    // scores over L
    const float* keyb = g_keyT + (size_t)n * LLEN * HID;
    for (int l = tid; l < LLEN; l += 256) {
        const float4* kr = (const float4*)(keyb + (size_t)l * HID);
        float s0 = 0.f, s1 = 0.f;
#pragma unroll 16
        for (int k = 0; k < HID / 8; ++k) {
            float4 k0 = kr[2 * k];
            float4 k1 = kr[2 * k + 1];
            s0 += k0.x * qsm[8 * k + 0] + k0.y * qsm[8 * k + 1] + k0.z * qsm[8 * k + 2] + k0.w * qsm[8 * k + 3];
            s1 += k1.x * qsm[8 * k + 4] + k1.y * qsm[8 * k + 5] + k1.z * qsm[8 * k + 6] + k1.w * qsm[8 * k + 7];
        }
        sc[l] = s0 + s1;
    }
    __syncthreads();

    // softmax (with max subtraction, like jax.nn.softmax)
    float m = -1e30f;
    for (int l = tid; l < LLEN; l += 256) m = fmaxf(m, sc[l]);
    red[tid] = m; __syncthreads();
    for (int s2 = 128; s2 > 0; s2 >>= 1) { if (tid < s2) red[tid] = fmaxf(red[tid], red[tid + s2]); __syncthreads(); }
    float M = red[0]; __syncthreads();

    float ps = 0.f;
    for (int l = tid; l < LLEN; l += 256) { float p = expf(sc[l] - M); sc[l] = p; ps += p; }
    red[tid] = ps; __syncthreads();
    for (int s2 = 128; s2 > 0; s2 >>= 1) { if (tid < s2) red[tid] += red[tid + s2]; __syncthreads(); }
    float S = red[0]; __syncthreads();

    // faithful post-softmax mask: attn = max(attn*mask, 1e-9), then renorm
    int sl = seq_lens[n];
    float invS = 1.f / S;
    float bsum = 0.f;
    for (int l = tid; l < LLEN; l += 256) {
        float a = sc[l] * invS;
        a = (l < sl) ? a : 0.f;
        a = fmaxf(a, 1e-9f);
        sc[l] = a;
        bsum += a;
    }
    red[tid] = bsum; __syncthreads();
    for (int s2 = 128; s2 > 0; s2 >>= 1) { if (tid < s2) red[tid] += red[tid + s2]; __syncthreads(); }
    float invB = 1.f / red[0]; __syncthreads();

    // ctx[h] = sum_l w_l * val[n,l,h]
    {
        const float* valb = g_valT + (size_t)n * LLEN * HID + tid;
        float a0 = 0.f, a1 = 0.f, a2 = 0.f, a3 = 0.f;
#pragma unroll 2
        for (int l = 0; l < LLEN; l += 4) {
            a0 += sc[l + 0] * valb[(size_t)(l + 0) * HID];
            a1 += sc[l + 1] * valb[(size_t)(l + 1) * HID];
            a2 += sc[l + 2] * valb[(size_t)(l + 2) * HID];
            a3 += sc[l + 3] * valb[(size_t)(l + 3) * HID];
        }
        float acc = ((a0 + a1) + (a2 + a3)) * invB;
        ctxs[tid] = acc;
        g_ctxT[tid * NB + n] = acc;   // consumed by next step's lstm0
    }
    __syncthreads();

    if (t < 0) return;   // initial-context call: no logits

    // hid = [ctx, q] @ Wo1.T + bo1
    {
        const float* wr = Wo1 + (size_t)tid * (HID + HID);
        float a = bo1[tid];
#pragma unroll 8
        for (int k = 0; k < HID; ++k) a += wr[k] * ctxs[k];
#pragma unroll 8
        for (int k = 0; k < HID; ++k) a += wr[HID + k] * qsm[k];
        hidv[tid] = a;
    }
    __syncthreads();

    // logits = hid @ embedding.T + bo2   (tied weights), warp per vocab entry
    int w = tid >> 5, lane = tid & 31;
    for (int v = w; v < VO; v += 8) {
        const float* er = emb + (size_t)v * HID;
        float a = 0.f;
#pragma unroll
        for (int h = lane; h < HID; h += 32) a += er[h] * hidv[h];
#pragma unroll
        for (int off = 16; off > 0; off >>= 1) a += __shfl_down_sync(0xffffffffu, a, off);
        if (lane == 0) out[(size_t)t * NB * VO + n * VO + v] = a + bo2[v];
    }
}

// ---------------- host ----------------
extern "C" void kernel_launch(void* const* d_in, const int* in_sizes, int n_in,
                              void* d_out, int out_size)
{
    const float* seqs      = (const float*)d_in[0];
    const int*   seq_lens  = (const int*)d_in[1];
    const int*   label_in  = (const int*)d_in[2];
    const float* embedding = (const float*)d_in[3];
    const float* inith     = (const float*)d_in[4];
    const float* initc     = (const float*)d_in[5];
    const float* W_ih0 = (const float*)d_in[6],  *W_hh0 = (const float*)d_in[7];
    const float* b_ih0 = (const float*)d_in[8],  *b_hh0 = (const float*)d_in[9];
    const float* W_ih1 = (const float*)d_in[10], *W_hh1 = (const float*)d_in[11];
    const float* b_ih1 = (const float*)d_in[12], *b_hh1 = (const float*)d_in[13];
    const float* W_ih2 = (const float*)d_in[14], *W_hh2 = (const float*)d_in[15];
    const float* b_ih2 = (const float*)d_in[16], *b_hh2 = (const float*)d_in[17];
    const float* Wq  = (const float*)d_in[18], *bq  = (const float*)d_in[19];
    const float* Wk  = (const float*)d_in[20], *bk  = (const float*)d_in[21];
    const float* Wv  = (const float*)d_in[22], *bv  = (const float*)d_in[23];
    const float* Wo1 = (const float*)d_in[24], *bo1 = (const float*)d_in[25];
    const float* bo2 = (const float*)d_in[26];
    float* out = (float*)d_out;

    const int SMEM_L0 = (512 + 256) * 33 * (int)sizeof(float);   // 101376 B
    const int SMEM_L1 = (256 + 256) * 33 * (int)sizeof(float);   // 67584 B
    cudaFuncSetAttribute(lstm_kernel, cudaFuncAttributeMaxDynamicSharedMemorySize, SMEM_L0);

    // precompute key/val projections (big GEMM)
    keyval_kernel<<<dim3(8, 1024), 256>>>(seqs, Wk, bk, Wv, bv);
    // init h/c state (buffer parity 0)
    init_kernel<<<32, 256>>>(inith, initc);
    // initial ctx from initial h2 (t = -1 -> no logits)
    attn_kernel<<<32, 256>>>(Wq, bq, seq_lens, Wo1, bo1, embedding, bo2, out, -1, 0);

    for (int t = 0; t < TS; ++t) {
        int pi = t & 1;   // read parity; write parity = 1-pi
        lstm_kernel<<<32, 256, SMEM_L0>>>(W_ih0, W_hh0, b_ih0, b_hh0, label_in, embedding, t, 0, pi, 512);
        lstm_kernel<<<32, 256, SMEM_L1>>>(W_ih1, W_hh1, b_ih1, b_hh1, nullptr, nullptr,   t, 1, pi, 256);
        lstm_kernel<<<32, 256, SMEM_L1>>>(W_ih2, W_hh2, b_ih2, b_hh2, nullptr, nullptr,   t, 2, pi, 256);
        attn_kernel<<<32, 256>>>(Wq, bq, seq_lens, Wo1, bo1, embedding, bo2, out, t, 1 - pi);
    }
}

// round 14
// speedup vs baseline: 2.7943x; 2.7943x over previous
#include <cuda_runtime.h>
#include <cuda_fp16.h>
#include <cstdint>

#define LLEN 2048
#define NB   32
#define TS   200
#define VO   34
#define DIN  512
#define HID  256
#define NL   (NB * LLEN)

// ---------------- device-global scratch (no allocation allowed) ----------------
__device__ float  g_keyf[(size_t)NL * HID];   // fp32 key (prologue scratch), 64MB
__device__ __half g_keyW[(size_t)NL * HID];   // key @ Wq, fp16, 32MB
__device__ __half g_val [(size_t)NL * HID];   // val, fp16, 32MB
__device__ float  g_wqT [HID * HID];          // Wq transposed
__device__ float  g_sb  [NL];                 // key . bq
__device__ float  g_scores[NL];               // per-step scores
__device__ float  g_hT[2][3][HID * NB];       // ping-pong h, transposed [jh][n]
__device__ float  g_c[3][HID * NB];           // c, transposed [jh][n]
__device__ float  g_ctxT[HID * NB];           // ctx, transposed [h][n]
__device__ int    g_sync;                     // grid barrier counter (self-resetting)

// ---------------- grid barrier (all 64 blocks resident; spin on L2 counter) ----------------
__device__ __forceinline__ void gridbar(int idx) {
    __syncthreads();
    if (threadIdx.x == 0) {
        __threadfence();
        atomicAdd(&g_sync, 1);
        int tgt = 64 * idx;
        while (*((volatile int*)&g_sync) < tgt) { __nanosleep(64); }
        __threadfence();
    }
    __syncthreads();
}

// ---------------- prologue GEMM 1: key(fp32) + val(fp16) ----------------
__global__ void gemm1_kernel(const float* __restrict__ seqs,
                             const float* __restrict__ Wk, const float* __restrict__ bk,
                             const float* __restrict__ Wv, const float* __restrict__ bv)
{
    __shared__ float As[16 * 65];
    __shared__ float Bs[16 * 65];
    int tid = threadIdx.x;
    int r0 = blockIdx.y * 64;
    int j0 = blockIdx.x * 64;
    int ty = tid >> 4, tx = tid & 15;

    float acc[4][4];
#pragma unroll
    for (int u = 0; u < 4; u++)
#pragma unroll
        for (int v = 0; v < 4; v++) acc[u][v] = 0.f;

    int lr = tid >> 2, kq = tid & 3;
    int rg = r0 + lr;
    int an = rg >> 11, al = rg & 2047;
    const float* arow = seqs + ((size_t)al * NB + an) * DIN + kq * 4;
    int jg = j0 + lr;
    const float* brow = (jg < HID) ? (Wk + (size_t)jg * DIN + kq * 4)
                                   : (Wv + (size_t)(jg - HID) * DIN + kq * 4);

    for (int kb = 0; kb < DIN; kb += 16) {
        float4 av  = *(const float4*)(arow + kb);
        float4 bvv = *(const float4*)(brow + kb);
        As[(kq * 4 + 0) * 65 + lr] = av.x;  As[(kq * 4 + 1) * 65 + lr] = av.y;
        As[(kq * 4 + 2) * 65 + lr] = av.z;  As[(kq * 4 + 3) * 65 + lr] = av.w;
        Bs[(kq * 4 + 0) * 65 + lr] = bvv.x; Bs[(kq * 4 + 1) * 65 + lr] = bvv.y;
        Bs[(kq * 4 + 2) * 65 + lr] = bvv.z; Bs[(kq * 4 + 3) * 65 + lr] = bvv.w;
        __syncthreads();
#pragma unroll
        for (int k = 0; k < 16; k++) {
            float a[4], b[4];
#pragma unroll
            for (int u = 0; u < 4; u++) a[u] = As[k * 65 + ty * 4 + u];
#pragma unroll
            for (int v = 0; v < 4; v++) b[v] = Bs[k * 65 + tx * 4 + v];
#pragma unroll
            for (int u = 0; u < 4; u++)
#pragma unroll
                for (int v = 0; v < 4; v++) acc[u][v] += a[u] * b[v];
        }
        __syncthreads();
    }
#pragma unroll
    for (int u = 0; u < 4; u++) {
        int r = r0 + ty * 4 + u;
#pragma unroll
        for (int v = 0; v < 4; v++) {
            int j = j0 + tx * 4 + v;
            if (j < HID) g_keyf[(size_t)r * HID + j] = acc[u][v] + bk[j];
            else         g_val [(size_t)r * HID + (j - HID)] = __float2half(acc[u][v] + bv[j - HID]);
        }
    }
}

// ---------------- Wq transpose ----------------
__global__ void wqt_kernel(const float* __restrict__ Wq)
{
    __shared__ float tl[32][33];
    int bx = blockIdx.x, by = blockIdx.y;
    int x = threadIdx.x, y = threadIdx.y;  // 32 x 8
    for (int i = 0; i < 32; i += 8) tl[y + i][x] = Wq[(by * 32 + y + i) * HID + bx * 32 + x];
    __syncthreads();
    for (int i = 0; i < 32; i += 8) g_wqT[(bx * 32 + y + i) * HID + by * 32 + x] = tl[x][y + i];
}

// ---------------- prologue GEMM 2: keyW(fp16) = key @ Wq ----------------
__global__ void gemm2_kernel()
{
    __shared__ float As[16 * 65];
    __shared__ float Bs[16 * 65];
    int tid = threadIdx.x;
    int r0 = blockIdx.y * 64;
    int j0 = blockIdx.x * 64;
    int ty = tid >> 4, tx = tid & 15;

    float acc[4][4];
#pragma unroll
    for (int u = 0; u < 4; u++)
#pragma unroll
        for (int v = 0; v < 4; v++) acc[u][v] = 0.f;

    int lr = tid >> 2, kq = tid & 3;
    const float* arow = g_keyf + (size_t)(r0 + lr) * HID + kq * 4;
    const float* brow = g_wqT  + (size_t)(j0 + lr) * HID + kq * 4;

    for (int kb = 0; kb < HID; kb += 16) {
        float4 av  = *(const float4*)(arow + kb);
        float4 bvv = *(const float4*)(brow + kb);
        As[(kq * 4 + 0) * 65 + lr] = av.x;  As[(kq * 4 + 1) * 65 + lr] = av.y;
        As[(kq * 4 + 2) * 65 + lr] = av.z;  As[(kq * 4 + 3) * 65 + lr] = av.w;
        Bs[(kq * 4 + 0) * 65 + lr] = bvv.x; Bs[(kq * 4 + 1) * 65 + lr] = bvv.y;
        Bs[(kq * 4 + 2) * 65 + lr] = bvv.z; Bs[(kq * 4 + 3) * 65 + lr] = bvv.w;
        __syncthreads();
#pragma unroll
        for (int k = 0; k < 16; k++) {
            float a[4], b[4];
#pragma unroll
            for (int u = 0; u < 4; u++) a[u] = As[k * 65 + ty * 4 + u];
#pragma unroll
            for (int v = 0; v < 4; v++) b[v] = Bs[k * 65 + tx * 4 + v];
#pragma unroll
            for (int u = 0; u < 4; u++)
#pragma unroll
                for (int v = 0; v < 4; v++) acc[u][v] += a[u] * b[v];
        }
        __syncthreads();
    }
#pragma unroll
    for (int u = 0; u < 4; u++) {
        int r = r0 + ty * 4 + u;
#pragma unroll
        for (int v = 0; v < 4; v++)
            g_keyW[(size_t)r * HID + j0 + tx * 4 + v] = __float2half(acc[u][v]);
    }
}

// ---------------- sb = key . bq ----------------
__global__ void sb_kernel(const float* __restrict__ bq)
{
    __shared__ float bqs[HID];
    int tid = threadIdx.x;
    bqs[tid] = bq[tid];
    __syncthreads();
    int r = blockIdx.x * 256 + tid;
    const float* kr = g_keyf + (size_t)r * HID;
    float a = 0.f;
#pragma unroll 8
    for (int k = 0; k < HID; ++k) a += kr[k] * bqs[k];
    g_sb[r] = a;
}

// ---------------- init h/c (transposed [jh][n]) ----------------
__global__ void init_kernel(const float* __restrict__ inith, const float* __restrict__ initc)
{
    int idx = blockIdx.x * 256 + threadIdx.x;  // 0..8191, jh = idx>>5, n = idx&31
#pragma unroll
    for (int layer = 0; layer < 3; ++layer) {
        g_hT[0][layer][idx] = inith[layer * HID + (idx >> 5)];
        g_c[layer][idx]     = initc[layer * HID + (idx >> 5)];
    }
}

// ---------------- helpers for the fused step kernel ----------------
__device__ __forceinline__ void copy_f4(float* dst, const float* src, int nf4) {
    const float4* s = (const float4*)src;
    float4* d = (float4*)dst;
    for (int i = threadIdx.x; i < nf4; i += 256) d[i] = s[i];
}

// stage 16 weight rows (4 jh x 4 gates) for this block: ws[r][0:dinW]=Wih, [dinW:+256]=Whh
__device__ __forceinline__ void stage_w(float* ws, const float* __restrict__ Wih,
                                        const float* __restrict__ Whh, int dinW) {
    int K = dinW + 256;
    int f4row = K >> 2, nIh = dinW >> 2;
    int total = 16 * f4row;
    int jb = blockIdx.x * 4;
    for (int idx = threadIdx.x; idx < total; idx += 256) {
        int r = idx / f4row, q = idx - r * f4row;
        int R = (r & 3) * 256 + jb + (r >> 2);   // gate*256 + jh
        float4 v = (q < nIh) ? ((const float4*)Wih)[(size_t)R * nIh + q]
                             : ((const float4*)Whh)[(size_t)R * 64 + (q - nIh)];
        ((float4*)(ws + r * K))[q] = v;
    }
}

// warp (jhl = w>>1, khalf = w&1) computes 4 gate partial dots; khalf=0 warps finish the cell.
__device__ __forceinline__ void lstm_compute(float* sm, const float* __restrict__ bih,
                                             const float* __restrict__ bhh,
                                             int K, int layer, int wpar) {
    float* xs = sm;             // [K][32]
    float* ws = sm + 24576;     // 16 rows x K
    float* pb = sm + 36864;     // [16][32]
    int tid = threadIdx.x, lane = tid & 31, w = tid >> 5;
    int jhl = w >> 1, kh = w & 1;
    int jh = blockIdx.x * 4 + jhl;
    int half = K >> 1, kb = kh * half;
    const float* r0 = ws + (jhl * 4 + 0) * K;
    const float* r1 = ws + (jhl * 4 + 1) * K;
    const float* r2 = ws + (jhl * 4 + 2) * K;
    const float* r3 = ws + (jhl * 4 + 3) * K;
    float a0 = 0.f, a1 = 0.f, a2 = 0.f, a3 = 0.f;
#pragma unroll 4
    for (int k = kb; k < kb + half; k += 4) {
        float4 w0 = *(const float4*)(r0 + k);
        float4 w1 = *(const float4*)(r1 + k);
        float4 w2 = *(const float4*)(r2 + k);
        float4 w3 = *(const float4*)(r3 + k);
        float x0 = xs[k * 32 + lane];
        float x1 = xs[k * 32 + 32 + lane];
        float x2 = xs[k * 32 + 64 + lane];
        float x3 = xs[k * 32 + 96 + lane];
        a0 += w0.x * x0 + w0.y * x1 + w0.z * x2 + w0.w * x3;
        a1 += w1.x * x0 + w1.y * x1 + w1.z * x2 + w1.w * x3;
        a2 += w2.x * x0 + w2.y * x1 + w2.z * x2 + w2.w * x3;
        a3 += w3.x * x0 + w3.y * x1 + w3.z * x2 + w3.w * x3;
    }
    if (kh) {
        pb[(jhl * 4 + 0) * 32 + lane] = a0;
        pb[(jhl * 4 + 1) * 32 + lane] = a1;
        pb[(jhl * 4 + 2) * 32 + lane] = a2;
        pb[(jhl * 4 + 3) * 32 + lane] = a3;
    }
    __syncthreads();
    if (!kh) {
        a0 += pb[(jhl * 4 + 0) * 32 + lane] + bih[jh]       + bhh[jh];
        a1 += pb[(jhl * 4 + 1) * 32 + lane] + bih[256 + jh] + bhh[256 + jh];
        a2 += pb[(jhl * 4 + 2) * 32 + lane] + bih[512 + jh] + bhh[512 + jh];
        a3 += pb[(jhl * 4 + 3) * 32 + lane] + bih[768 + jh] + bhh[768 + jh];
        float si = 1.f / (1.f + expf(-a0));
        float sf = 1.f / (1.f + expf(-a1));
        float tg = tanhf(a2);
        float so = 1.f / (1.f + expf(-a3));
        int ci = jh * 32 + lane;
        float cn = sf * g_c[layer][ci] + si * tg;
        g_c[layer][ci] = cn;
        g_hT[wpar][layer][ci] = so * tanhf(cn);
    }
    __syncthreads();
}

// ---------------- fused decode step: lstm x3 + scores + softmax/ctx + tail ----------------
// grid 64 blocks x 256 threads, all co-resident (1 block/SM). Internal grid barriers.
__global__ void __launch_bounds__(256, 1) step_kernel(
    const float* __restrict__ W_ih0, const float* __restrict__ W_hh0,
    const float* __restrict__ b_ih0, const float* __restrict__ b_hh0,
    const float* __restrict__ W_ih1, const float* __restrict__ W_hh1,
    const float* __restrict__ b_ih1, const float* __restrict__ b_hh1,
    const float* __restrict__ W_ih2, const float* __restrict__ W_hh2,
    const float* __restrict__ b_ih2, const float* __restrict__ b_hh2,
    const int* __restrict__ label_in, const float* __restrict__ emb,
    const int* __restrict__ seq_lens,
    const float* __restrict__ Wq, const float* __restrict__ bq,
    const float* __restrict__ Wo1, const float* __restrict__ bo1,
    const float* __restrict__ bo2,
    float* __restrict__ out, int t, int pi, int initmode)
{
    extern __shared__ float sm[];
    __shared__ int labs[NB];
    int tid = threadIdx.x, b = blockIdx.x;
    int wpar = 1 - pi;
    int hp = initmode ? pi : wpar;   // parity holding h2 for attention
    int bar = 0;

    if (!initmode) {
        // ---- layer 0: x = [ctx(256) | emb(256) | h0_prev(256)] ----
        if (tid < NB) labs[tid] = label_in[tid * TS + t];
        copy_f4(sm, g_ctxT, 2048);                       // k 0..255
        copy_f4(sm + 16384, g_hT[pi][0], 2048);          // k 512..767
        stage_w(sm + 24576, W_ih0, W_hh0, 512);
        __syncthreads();                                 // labs ready
        for (int idx = tid; idx < 8192; idx += 256) {    // k 256..511 (emb gather)
            int n = idx & 31, k2 = idx >> 5;
            sm[8192 + idx] = emb[(size_t)labs[n] * HID + k2];
        }
        __syncthreads();
        lstm_compute(sm, b_ih0, b_hh0, 768, 0, wpar);
        gridbar(++bar);

        // ---- layer 1: x = [h0_new | h1_prev] ----
        copy_f4(sm, g_hT[wpar][0], 2048);
        copy_f4(sm + 8192, g_hT[pi][1], 2048);
        stage_w(sm + 24576, W_ih1, W_hh1, 256);
        __syncthreads();
        lstm_compute(sm, b_ih1, b_hh1, 512, 1, wpar);
        gridbar(++bar);

        // ---- layer 2: x = [h1_new | h2_prev] ----
        copy_f4(sm, g_hT[wpar][1], 2048);
        copy_f4(sm + 8192, g_hT[pi][2], 2048);
        stage_w(sm + 24576, W_ih2, W_hh2, 256);
        __syncthreads();
        lstm_compute(sm, b_ih2, b_hh2, 512, 2, wpar);
        gridbar(++bar);
    }

    // ---- scores: block (n = b>>1, lhalf = b&1), 1024 l each ----
    {
        float* h2s = sm + 2304;
        int nb = b >> 1, lh = b & 1;
        h2s[tid] = g_hT[hp][2][tid * 32 + nb];
        __syncthreads();
        int lbase = lh * 1024;
#pragma unroll
        for (int i = 0; i < 4; i++) {
            int l = lbase + i * 256 + tid;
            const uint4* kr = (const uint4*)(g_keyW + ((size_t)nb * LLEN + l) * HID);
            float acc = 0.f;
#pragma unroll
            for (int kk = 0; kk < 32; kk++) {
                uint4 u = kr[kk];
                float2 f0 = __half22float2(*reinterpret_cast<__half2*>(&u.x));
                float2 f1 = __half22float2(*reinterpret_cast<__half2*>(&u.y));
                float2 f2 = __half22float2(*reinterpret_cast<__half2*>(&u.z));
                float2 f3 = __half22float2(*reinterpret_cast<__half2*>(&u.w));
                acc += f0.x * h2s[kk * 8 + 0] + f0.y * h2s[kk * 8 + 1]
                     + f1.x * h2s[kk * 8 + 2] + f1.y * h2s[kk * 8 + 3]
                     + f2.x * h2s[kk * 8 + 4] + f2.y * h2s[kk * 8 + 5]
                     + f3.x * h2s[kk * 8 + 6] + f3.y * h2s[kk * 8 + 7];
            }
            g_scores[nb * LLEN + l] = acc + g_sb[nb * LLEN + l];
        }
    }
    gridbar(++bar);

    // ---- softmax + mask + ctx: block (n = b>>1, hhalf = b&1), 128 h each ----
    {
        float* sc   = sm;            // [2048]
        float* red  = sm + 2048;     // [256]
        float* part = sm + 2560;     // [4][128]
        int nb = b >> 1, hbase = (b & 1) * 128;

        float lv[8];
        float m = -1e30f;
#pragma unroll
        for (int i = 0; i < 8; i++) { lv[i] = g_scores[nb * LLEN + tid + i * 256]; m = fmaxf(m, lv[i]); }
        red[tid] = m; __syncthreads();
        for (int s = 128; s > 0; s >>= 1) { if (tid < s) red[tid] = fmaxf(red[tid], red[tid + s]); __syncthreads(); }
        float M = red[0]; __syncthreads();

        float ps = 0.f;
#pragma unroll
        for (int i = 0; i < 8; i++) { float p = expf(lv[i] - M); sc[tid + i * 256] = p; ps += p; }
        red[tid] = ps; __syncthreads();
        for (int s = 128; s > 0; s >>= 1) { if (tid < s) red[tid] += red[tid + s]; __syncthreads(); }
        float invS = 1.f / red[0]; __syncthreads();

        int sl = seq_lens[nb];
        float bs = 0.f;
#pragma unroll
        for (int i = 0; i < 8; i++) {
            int l = tid + i * 256;
            float a = sc[l] * invS;
            a = (l < sl) ? a : 0.f;
            a = fmaxf(a, 1e-9f);
            sc[l] = a; bs += a;
        }
        red[tid] = bs; __syncthreads();
        for (int s = 128; s > 0; s >>= 1) { if (tid < s) red[tid] += red[tid + s]; __syncthreads(); }
        float invB = 1.f / red[0]; __syncthreads();
#pragma unroll
        for (int i = 0; i < 8; i++) sc[tid + i * 256] *= invB;
        __syncthreads();

        int ls = tid >> 6, li = tid & 63;   // 4 l-slices x 64 threads (2 h each)
        const __half* vb = g_val + (size_t)nb * LLEN * HID + hbase + 2 * li;
        float A0 = 0.f, A1 = 0.f;
#pragma unroll 4
        for (int l = ls; l < LLEN; l += 4) {
            float wgt = sc[l];
            float2 f = __half22float2(*(const __half2*)(vb + (size_t)l * HID));
            A0 += wgt * f.x; A1 += wgt * f.y;
        }
        part[ls * 128 + 2 * li]     = A0;
        part[ls * 128 + 2 * li + 1] = A1;
        __syncthreads();
        if (tid < 128) {
            float s = part[tid] + part[128 + tid] + part[256 + tid] + part[384 + tid];
            g_ctxT[(hbase + tid) * 32 + nb] = s;
        }
    }

    if (!initmode) {
        gridbar(++bar);   // ctx visible to tail blocks

        if (b < NB) {     // ---- tail: q, hid, tied logits for batch n = b ----
            float* h2s  = sm + 2304;
            float* qv   = sm + 3072;
            float* ctxs = sm + 3328;
            float* hidv = sm + 3584;
            int n = b;
            h2s[tid]  = g_hT[hp][2][tid * 32 + n];
            ctxs[tid] = __ldcv(&g_ctxT[tid * 32 + n]);   // bypass L1 (stale from lstm0 staging)
            __syncthreads();
            {
                const float* wr = Wq + (size_t)tid * HID;
                float a = bq[tid];
#pragma unroll 8
                for (int k = 0; k < HID; ++k) a += wr[k] * h2s[k];
                qv[tid] = a;
            }
            __syncthreads();
            {
                const float* wr = Wo1 + (size_t)tid * (2 * HID);
                float a = bo1[tid];
#pragma unroll 8
                for (int k = 0; k < HID; ++k) a += wr[k] * ctxs[k];
#pragma unroll 8
                for (int k = 0; k < HID; ++k) a += wr[HID + k] * qv[k];
                hidv[tid] = a;
            }
            __syncthreads();
            int w = tid >> 5, lane = tid & 31;
            for (int v = w; v < VO; v += 8) {
                const float* er = emb + (size_t)v * HID;
                float a = 0.f;
#pragma unroll
                for (int h = lane; h < HID; h += 32) a += er[h] * hidv[h];
#pragma unroll
                for (int off = 16; off > 0; off >>= 1) a += __shfl_down_sync(0xffffffffu, a, off);
                if (lane == 0) out[(size_t)t * NB * VO + n * VO + v] = a + bo2[v];
            }
        }
    }

    // final arrive (no wait); last arriver resets the barrier counter for the next launch
    __syncthreads();
    if (tid == 0) {
        __threadfence();
        int old = atomicAdd(&g_sync, 1);
        if (old == bar * 64 + 63) { g_sync = 0; __threadfence(); }
    }
}

// ---------------- host ----------------
extern "C" void kernel_launch(void* const* d_in, const int* in_sizes, int n_in,
                              void* d_out, int out_size)
{
    const float* seqs      = (const float*)d_in[0];
    const int*   seq_lens  = (const int*)d_in[1];
    const int*   label_in  = (const int*)d_in[2];
    const float* embedding = (const float*)d_in[3];
    const float* inith     = (const float*)d_in[4];
    const float* initc     = (const float*)d_in[5];
    const float* W_ih0 = (const float*)d_in[6],  *W_hh0 = (const float*)d_in[7];
    const float* b_ih0 = (const float*)d_in[8],  *b_hh0 = (const float*)d_in[9];
    const float* W_ih1 = (const float*)d_in[10], *W_hh1 = (const float*)d_in[11];
    const float* b_ih1 = (const float*)d_in[12], *b_hh1 = (const float*)d_in[13];
    const float* W_ih2 = (const float*)d_in[14], *W_hh2 = (const float*)d_in[15];
    const float* b_ih2 = (const float*)d_in[16], *b_hh2 = (const float*)d_in[17];
    const float* Wq  = (const float*)d_in[18], *bq  = (const float*)d_in[19];
    const float* Wk  = (const float*)d_in[20], *bk  = (const float*)d_in[21];
    const float* Wv  = (const float*)d_in[22], *bv  = (const float*)d_in[23];
    const float* Wo1 = (const float*)d_in[24], *bo1 = (const float*)d_in[25];
    const float* bo2 = (const float*)d_in[26];
    float* out = (float*)d_out;

    const int SMEMB = (24576 + 12288 + 512) * (int)sizeof(float);   // 149504 B
    cudaFuncSetAttribute(step_kernel, cudaFuncAttributeMaxDynamicSharedMemorySize, SMEMB);

    // prologue: key/val, Wq^T, keyW = key@Wq, sb = key.bq, state init
    gemm1_kernel<<<dim3(8, 1024), 256>>>(seqs, Wk, bk, Wv, bv);
    wqt_kernel<<<dim3(8, 8), dim3(32, 8)>>>(Wq);
    gemm2_kernel<<<dim3(4, 1024), 256>>>();
    sb_kernel<<<256, 256>>>(bq);
    init_kernel<<<32, 256>>>(inith, initc);

    // initial ctx from initial h2 (initmode: scores+ctx only)
    step_kernel<<<64, 256, SMEMB>>>(W_ih0, W_hh0, b_ih0, b_hh0,
                                    W_ih1, W_hh1, b_ih1, b_hh1,
                                    W_ih2, W_hh2, b_ih2, b_hh2,
                                    label_in, embedding, seq_lens,
                                    Wq, bq, Wo1, bo1, bo2, out, -1, 0, 1);

    for (int t = 0; t < TS; ++t) {
        step_kernel<<<64, 256, SMEMB>>>(W_ih0, W_hh0, b_ih0, b_hh0,
                                        W_ih1, W_hh1, b_ih1, b_hh1,
                                        W_ih2, W_hh2, b_ih2, b_hh2,
                                        label_in, embedding, seq_lens,
                                        Wq, bq, Wo1, bo1, bo2, out, t, t & 1, 0);
    }
}

// round 17
// speedup vs baseline: 7.5241x; 2.6927x over previous
#include <cuda_runtime.h>
#include <cuda_fp16.h>
#include <cstdint>

#define LLEN 2048
#define NB   32
#define TS   200
#define VO   34
#define DIN  512
#define HID  256
#define NL   (NB * LLEN)
#define NBLK 128

// ---------------- device-global scratch (no allocation allowed) ----------------
__device__ float  g_keyf[(size_t)NL * HID];   // fp32 key (prologue scratch), 64MB
__device__ __half g_keyW[(size_t)NL * HID];   // key @ Wq, fp16, 32MB
__device__ __half g_val [(size_t)NL * HID];   // val, fp16, 32MB
__device__ float  g_wqT [HID * HID];          // Wq transposed
__device__ float  g_sb  [NL];                 // key . bq
__device__ float  g_scores[NL];               // per-step scores
__device__ float  g_hT[2][3][HID * NB];       // ping-pong h, transposed [jh][n]
__device__ float  g_c[3][HID * NB];           // c, transposed [jh][n]
__device__ float  g_ctxT[HID * NB];           // ctx, transposed [h][n]
__device__ int    g_sync;                     // grid barrier counter (self-resetting)

// ---------------- grid barrier (all NBLK blocks resident; spin on L2 counter) ----------------
__device__ __forceinline__ void gridbar(int idx) {
    __syncthreads();
    if (threadIdx.x == 0) {
        __threadfence();
        atomicAdd(&g_sync, 1);
        int tgt = NBLK * idx;
        while (*((volatile int*)&g_sync) < tgt) { __nanosleep(64); }
        __threadfence();
    }
    __syncthreads();
}

// ---------------- prologue GEMM 1: key(fp32) + val(fp16) ----------------
__global__ void gemm1_kernel(const float* __restrict__ seqs,
                             const float* __restrict__ Wk, const float* __restrict__ bk,
                             const float* __restrict__ Wv, const float* __restrict__ bv)
{
    __shared__ float As[16 * 65];
    __shared__ float Bs[16 * 65];
    int tid = threadIdx.x;
    int r0 = blockIdx.y * 64;
    int j0 = blockIdx.x * 64;
    int ty = tid >> 4, tx = tid & 15;

    float acc[4][4];
#pragma unroll
    for (int u = 0; u < 4; u++)
#pragma unroll
        for (int v = 0; v < 4; v++) acc[u][v] = 0.f;

    int lr = tid >> 2, kq = tid & 3;
    int rg = r0 + lr;
    int an = rg >> 11, al = rg & 2047;
    const float* arow = seqs + ((size_t)al * NB + an) * DIN + kq * 4;
    int jg = j0 + lr;
    const float* brow = (jg < HID) ? (Wk + (size_t)jg * DIN + kq * 4)
                                   : (Wv + (size_t)(jg - HID) * DIN + kq * 4);

    for (int kb = 0; kb < DIN; kb += 16) {
        float4 av  = *(const float4*)(arow + kb);
        float4 bvv = *(const float4*)(brow + kb);
        As[(kq * 4 + 0) * 65 + lr] = av.x;  As[(kq * 4 + 1) * 65 + lr] = av.y;
        As[(kq * 4 + 2) * 65 + lr] = av.z;  As[(kq * 4 + 3) * 65 + lr] = av.w;
        Bs[(kq * 4 + 0) * 65 + lr] = bvv.x; Bs[(kq * 4 + 1) * 65 + lr] = bvv.y;
        Bs[(kq * 4 + 2) * 65 + lr] = bvv.z; Bs[(kq * 4 + 3) * 65 + lr] = bvv.w;
        __syncthreads();
#pragma unroll
        for (int k = 0; k < 16; k++) {
            float a[4], b[4];
#pragma unroll
            for (int u = 0; u < 4; u++) a[u] = As[k * 65 + ty * 4 + u];
#pragma unroll
            for (int v = 0; v < 4; v++) b[v] = Bs[k * 65 + tx * 4 + v];
#pragma unroll
            for (int u = 0; u < 4; u++)
#pragma unroll
                for (int v = 0; v < 4; v++) acc[u][v] += a[u] * b[v];
        }
        __syncthreads();
    }
#pragma unroll
    for (int u = 0; u < 4; u++) {
        int r = r0 + ty * 4 + u;
#pragma unroll
        for (int v = 0; v < 4; v++) {
            int j = j0 + tx * 4 + v;
            if (j < HID) g_keyf[(size_t)r * HID + j] = acc[u][v] + bk[j];
            else         g_val [(size_t)r * HID + (j - HID)] = __float2half(acc[u][v] + bv[j - HID]);
        }
    }
}

// ---------------- Wq transpose ----------------
__global__ void wqt_kernel(const float* __restrict__ Wq)
{
    __shared__ float tl[32][33];
    int bx = blockIdx.x, by = blockIdx.y;
    int x = threadIdx.x, y = threadIdx.y;  // 32 x 8
    for (int i = 0; i < 32; i += 8) tl[y + i][x] = Wq[(by * 32 + y + i) * HID + bx * 32 + x];
    __syncthreads();
    for (int i = 0; i < 32; i += 8) g_wqT[(bx * 32 + y + i) * HID + by * 32 + x] = tl[x][y + i];
}

// ---------------- prologue GEMM 2: keyW(fp16) = key @ Wq ----------------
__global__ void gemm2_kernel()
{
    __shared__ float As[16 * 65];
    __shared__ float Bs[16 * 65];
    int tid = threadIdx.x;
    int r0 = blockIdx.y * 64;
    int j0 = blockIdx.x * 64;
    int ty = tid >> 4, tx = tid & 15;

    float acc[4][4];
#pragma unroll
    for (int u = 0; u < 4; u++)
#pragma unroll
        for (int v = 0; v < 4; v++) acc[u][v] = 0.f;

    int lr = tid >> 2, kq = tid & 3;
    const float* arow = g_keyf + (size_t)(r0 + lr) * HID + kq * 4;
    const float* brow = g_wqT  + (size_t)(j0 + lr) * HID + kq * 4;

    for (int kb = 0; kb < HID; kb += 16) {
        float4 av  = *(const float4*)(arow + kb);
        float4 bvv = *(const float4*)(brow + kb);
        As[(kq * 4 + 0) * 65 + lr] = av.x;  As[(kq * 4 + 1) * 65 + lr] = av.y;
        As[(kq * 4 + 2) * 65 + lr] = av.z;  As[(kq * 4 + 3) * 65 + lr] = av.w;
        Bs[(kq * 4 + 0) * 65 + lr] = bvv.x; Bs[(kq * 4 + 1) * 65 + lr] = bvv.y;
        Bs[(kq * 4 + 2) * 65 + lr] = bvv.z; Bs[(kq * 4 + 3) * 65 + lr] = bvv.w;
        __syncthreads();
#pragma unroll
        for (int k = 0; k < 16; k++) {
            float a[4], b[4];
#pragma unroll
            for (int u = 0; u < 4; u++) a[u] = As[k * 65 + ty * 4 + u];
#pragma unroll
            for (int v = 0; v < 4; v++) b[v] = Bs[k * 65 + tx * 4 + v];
#pragma unroll
            for (int u = 0; u < 4; u++)
#pragma unroll
                for (int v = 0; v < 4; v++) acc[u][v] += a[u] * b[v];
        }
        __syncthreads();
    }
#pragma unroll
    for (int u = 0; u < 4; u++) {
        int r = r0 + ty * 4 + u;
#pragma unroll
        for (int v = 0; v < 4; v++)
            g_keyW[(size_t)r * HID + j0 + tx * 4 + v] = __float2half(acc[u][v]);
    }
}

// ---------------- sb = key . bq ----------------
__global__ void sb_kernel(const float* __restrict__ bq)
{
    __shared__ float bqs[HID];
    int tid = threadIdx.x;
    bqs[tid] = bq[tid];
    __syncthreads();
    int r = blockIdx.x * 256 + tid;
    const float* kr = g_keyf + (size_t)r * HID;
    float a = 0.f;
#pragma unroll 8
    for (int k = 0; k < HID; ++k) a += kr[k] * bqs[k];
    g_sb[r] = a;
}

// ---------------- init h/c (transposed [jh][n]) ----------------
__global__ void init_kernel(const float* __restrict__ inith, const float* __restrict__ initc)
{
    int idx = blockIdx.x * 256 + threadIdx.x;  // 0..8191, jh = idx>>5, n = idx&31
#pragma unroll
    for (int layer = 0; layer < 3; ++layer) {
        g_hT[0][layer][idx] = inith[layer * HID + (idx >> 5)];
        g_c[layer][idx]     = initc[layer * HID + (idx >> 5)];
    }
}

// ---------------- fused step kernel helpers ----------------
// smem float layout (dynamic):
//   xs  [0 .. 24576)      inputs [k][32]
//   ws  [24576 .. 30720)  8 weight rows x K (K<=768)
//   pb  [30720 .. 31488)  partials [8 rows][3 quarters][32]
// attention phases reuse:
//   sc 0..2048, red 2048..2304, h2s 2304..2560, part 2560..4608,
//   catv 4608..5120, hidv 5120..5376
#define SMF 31488

__device__ __forceinline__ void copy_f4(float* dst, const float* src, int nf4) {
    const float4* s = (const float4*)src;
    float4* d = (float4*)dst;
    for (int i = threadIdx.x; i < nf4; i += 256) d[i] = s[i];
}

// stage 8 weight rows (2 jh x 4 gates): ws[r][0:dinW]=Wih row, [dinW:+256]=Whh row
__device__ __forceinline__ void stage_w(float* ws, const float* __restrict__ Wih,
                                        const float* __restrict__ Whh, int dinW) {
    int K = dinW + 256;
    int f4row = K >> 2, nIh = dinW >> 2;
    int total = 8 * f4row;
    int jb = blockIdx.x * 2;
    for (int idx = threadIdx.x; idx < total; idx += 256) {
        int r = idx / f4row, q = idx - r * f4row;
        int R = (r & 3) * 256 + jb + (r >> 2);   // gate*256 + jh
        float4 v = (q < nIh) ? ((const float4*)Wih)[(size_t)R * nIh + q]
                             : ((const float4*)Whh)[(size_t)R * 64 + (q - nIh)];
        ((float4*)(ws + r * K))[q] = v;
    }
}

// warp w: jhl = w&1, kq = w>>1 (K quarter). kq==0 warps finish the cell.
__device__ __forceinline__ void lstm_compute(float* sm, const float* __restrict__ bih,
                                             const float* __restrict__ bhh,
                                             int K, int layer, int wpar) {
    float* xs = sm;
    float* ws = sm + 24576;
    float* pb = sm + 30720;
    int tid = threadIdx.x, lane = tid & 31, w = tid >> 5;
    int jhl = w & 1, kq = w >> 1;
    int jh = blockIdx.x * 2 + jhl;
    int qlen = K >> 2, kb = kq * qlen;
    const float* r0 = ws + (jhl * 4 + 0) * K;
    const float* r1 = ws + (jhl * 4 + 1) * K;
    const float* r2 = ws + (jhl * 4 + 2) * K;
    const float* r3 = ws + (jhl * 4 + 3) * K;
    float a0 = 0.f, a1 = 0.f, a2 = 0.f, a3 = 0.f;
#pragma unroll 4
    for (int k = kb; k < kb + qlen; k += 4) {
        float4 w0 = *(const float4*)(r0 + k);
        float4 w1 = *(const float4*)(r1 + k);
        float4 w2 = *(const float4*)(r2 + k);
        float4 w3 = *(const float4*)(r3 + k);
        float x0 = xs[k * 32 + lane];
        float x1 = xs[k * 32 + 32 + lane];
        float x2 = xs[k * 32 + 64 + lane];
        float x3 = xs[k * 32 + 96 + lane];
        a0 += w0.x * x0 + w0.y * x1 + w0.z * x2 + w0.w * x3;
        a1 += w1.x * x0 + w1.y * x1 + w1.z * x2 + w1.w * x3;
        a2 += w2.x * x0 + w2.y * x1 + w2.z * x2 + w2.w * x3;
        a3 += w3.x * x0 + w3.y * x1 + w3.z * x2 + w3.w * x3;
    }
    if (kq) {
        int p = kq - 1;
        pb[((jhl * 4 + 0) * 3 + p) * 32 + lane] = a0;
        pb[((jhl * 4 + 1) * 3 + p) * 32 + lane] = a1;
        pb[((jhl * 4 + 2) * 3 + p) * 32 + lane] = a2;
        pb[((jhl * 4 + 3) * 3 + p) * 32 + lane] = a3;
    }
    __syncthreads();
    if (!kq) {
#pragma unroll
        for (int p = 0; p < 3; p++) {
            a0 += pb[((jhl * 4 + 0) * 3 + p) * 32 + lane];
            a1 += pb[((jhl * 4 + 1) * 3 + p) * 32 + lane];
            a2 += pb[((jhl * 4 + 2) * 3 + p) * 32 + lane];
            a3 += pb[((jhl * 4 + 3) * 3 + p) * 32 + lane];
        }
        a0 += bih[jh]       + bhh[jh];
        a1 += bih[256 + jh] + bhh[256 + jh];
        a2 += bih[512 + jh] + bhh[512 + jh];
        a3 += bih[768 + jh] + bhh[768 + jh];
        float si = 1.f / (1.f + expf(-a0));
        float sf = 1.f / (1.f + expf(-a1));
        float tg = tanhf(a2);
        float so = 1.f / (1.f + expf(-a3));
        int ci = jh * 32 + lane;
        float cn = sf * g_c[layer][ci] + si * tg;
        g_c[layer][ci] = cn;
        g_hT[wpar][layer][ci] = so * tanhf(cn);
    }
    __syncthreads();
}

// ---------------- fused decode step ----------------
__global__ void __launch_bounds__(256, 1) step_kernel(
    const float* __restrict__ W_ih0, const float* __restrict__ W_hh0,
    const float* __restrict__ b_ih0, const float* __restrict__ b_hh0,
    const float* __restrict__ W_ih1, const float* __restrict__ W_hh1,
    const float* __restrict__ b_ih1, const float* __restrict__ b_hh1,
    const float* __restrict__ W_ih2, const float* __restrict__ W_hh2,
    const float* __restrict__ b_ih2, const float* __restrict__ b_hh2,
    const int* __restrict__ label_in, const float* __restrict__ emb,
    const int* __restrict__ seq_lens,
    const float* __restrict__ Wq, const float* __restrict__ bq,
    const float* __restrict__ Wo1, const float* __restrict__ bo1,
    const float* __restrict__ bo2,
    float* __restrict__ out, int t, int pi, int initmode)
{
    extern __shared__ float sm[];
    __shared__ int labs[NB];
    int tid = threadIdx.x, b = blockIdx.x;
    int wpar = 1 - pi;
    int hp = initmode ? pi : wpar;
    int bar = 0;

    if (!initmode) {
        // ---- layer 0: x = [ctx(256) | emb(256) | h0_prev(256)] ----
        if (tid < NB) labs[tid] = label_in[tid * TS + t];
        copy_f4(sm, g_ctxT, 2048);
        copy_f4(sm + 16384, g_hT[pi][0], 2048);
        stage_w(sm + 24576, W_ih0, W_hh0, 512);
        __syncthreads();
        for (int idx = tid; idx < 8192; idx += 256) {
            int n = idx & 31, k2 = idx >> 5;
            sm[8192 + idx] = emb[(size_t)labs[n] * HID + k2];
        }
        __syncthreads();
        lstm_compute(sm, b_ih0, b_hh0, 768, 0, wpar);
        gridbar(++bar);

        // ---- layer 1 ----
        copy_f4(sm, g_hT[wpar][0], 2048);
        copy_f4(sm + 8192, g_hT[pi][1], 2048);
        stage_w(sm + 24576, W_ih1, W_hh1, 256);
        __syncthreads();
        lstm_compute(sm, b_ih1, b_hh1, 512, 1, wpar);
        gridbar(++bar);

        // ---- layer 2 ----
        copy_f4(sm, g_hT[wpar][1], 2048);
        copy_f4(sm + 8192, g_hT[pi][2], 2048);
        stage_w(sm + 24576, W_ih2, W_hh2, 256);
        __syncthreads();
        lstm_compute(sm, b_ih2, b_hh2, 512, 2, wpar);
        gridbar(++bar);
    }

    // ---- scores: block (n = b>>2, lq = b&3) covers 512 l. Thread pair per l-row. ----
    {
        float* h2s = sm + 2304;
        int nb = b >> 2, lbase = (b & 3) * 512;
        h2s[tid] = g_hT[hp][2][tid * 32 + nb];
        __syncthreads();
        int lidx = tid >> 1, kh = tid & 1;
#pragma unroll
        for (int p = 0; p < 4; p++) {
            int l = lbase + p * 128 + lidx;
            const uint4* kp = (const uint4*)(g_keyW + ((size_t)nb * LLEN + l) * HID + kh * 128);
            float acc = 0.f;
#pragma unroll
            for (int hv = 0; hv < 2; hv++) {
                uint4 u[8];
#pragma unroll
                for (int j = 0; j < 8; j++) u[j] = kp[hv * 8 + j];
#pragma unroll
                for (int j = 0; j < 8; j++) {
                    int base = kh * 128 + hv * 64 + j * 8;
                    float2 f0 = __half22float2(*reinterpret_cast<__half2*>(&u[j].x));
                    float2 f1 = __half22float2(*reinterpret_cast<__half2*>(&u[j].y));
                    float2 f2 = __half22float2(*reinterpret_cast<__half2*>(&u[j].z));
                    float2 f3 = __half22float2(*reinterpret_cast<__half2*>(&u[j].w));
                    acc += f0.x * h2s[base + 0] + f0.y * h2s[base + 1]
                         + f1.x * h2s[base + 2] + f1.y * h2s[base + 3]
                         + f2.x * h2s[base + 4] + f2.y * h2s[base + 5]
                         + f3.x * h2s[base + 6] + f3.y * h2s[base + 7];
                }
            }
            float other = __shfl_xor_sync(0xffffffffu, acc, 1);
            if (kh == 0) g_scores[nb * LLEN + l] = acc + other + g_sb[nb * LLEN + l];
        }
    }
    gridbar(++bar);

    // ---- softmax + mask + ctx: block (n = b>>2, hq = b&3) covers 64 h ----
    {
        float* sc   = sm;
        float* red  = sm + 2048;
        float* part = sm + 2560;   // [32][64]
        int nb = b >> 2, hbase = (b & 3) * 64;

        float lv[8];
        float m = -1e30f;
#pragma unroll
        for (int i = 0; i < 8; i++) { lv[i] = g_scores[nb * LLEN + tid + i * 256]; m = fmaxf(m, lv[i]); }
        red[tid] = m; __syncthreads();
        for (int s = 128; s > 0; s >>= 1) { if (tid < s) red[tid] = fmaxf(red[tid], red[tid + s]); __syncthreads(); }
        float M = red[0]; __syncthreads();

        float ps = 0.f;
#pragma unroll
        for (int i = 0; i < 8; i++) { float p = expf(lv[i] - M); sc[tid + i * 256] = p; ps += p; }
        red[tid] = ps; __syncthreads();
        for (int s = 128; s > 0; s >>= 1) { if (tid < s) red[tid] += red[tid + s]; __syncthreads(); }
        float invS = 1.f / red[0]; __syncthreads();

        int sl = seq_lens[nb];
        float bs = 0.f;
#pragma unroll
        for (int i = 0; i < 8; i++) {
            int l = tid + i * 256;
            float a = sc[l] * invS;
            a = (l < sl) ? a : 0.f;
            a = fmaxf(a, 1e-9f);
            sc[l] = a; bs += a;
        }
        red[tid] = bs; __syncthreads();
        for (int s = 128; s > 0; s >>= 1) { if (tid < s) red[tid] += red[tid + s]; __syncthreads(); }
        float invB = 1.f / red[0]; __syncthreads();
#pragma unroll
        for (int i = 0; i < 8; i++) sc[tid + i * 256] *= invB;
        __syncthreads();

        // thread (lrow = tid>>3, hg = tid&7): 8 h cols each, 16B loads, l stride 32
        int lrow = tid >> 3, hg = tid & 7;
        const __half* vb = g_val + (size_t)nb * LLEN * HID + hbase + hg * 8;
        float acc[8];
#pragma unroll
        for (int i = 0; i < 8; i++) acc[i] = 0.f;
#pragma unroll 4
        for (int pass = 0; pass < 64; ++pass) {
            int l = lrow + pass * 32;
            uint4 u = *(const uint4*)(vb + (size_t)l * HID);
            float wgt = sc[l];
            float2 f0 = __half22float2(*reinterpret_cast<__half2*>(&u.x));
            float2 f1 = __half22float2(*reinterpret_cast<__half2*>(&u.y));
            float2 f2 = __half22float2(*reinterpret_cast<__half2*>(&u.z));
            float2 f3 = __half22float2(*reinterpret_cast<__half2*>(&u.w));
            acc[0] += wgt * f0.x; acc[1] += wgt * f0.y;
            acc[2] += wgt * f1.x; acc[3] += wgt * f1.y;
            acc[4] += wgt * f2.x; acc[5] += wgt * f2.y;
            acc[6] += wgt * f3.x; acc[7] += wgt * f3.y;
        }
#pragma unroll
        for (int i = 0; i < 8; i++) part[lrow * 64 + hg * 8 + i] = acc[i];
        __syncthreads();
        if (tid < 64) {
            float s = 0.f;
#pragma unroll
            for (int r = 0; r < 32; r++) s += part[r * 64 + tid];
            g_ctxT[(hbase + tid) * 32 + nb] = s;
        }
        __syncthreads();
    }

    if (!initmode) {
        gridbar(++bar);

        if (b < NB) {   // ---- tail for batch n = b ----
            float* h2s  = sm + 2304;
            float* catv = sm + 4608;   // [ctx(256) | q(256)]
            float* hidv = sm + 5120;
            int n = b;
            int w = tid >> 5, lane = tid & 31;
            h2s[tid]  = g_hT[hp][2][tid * 32 + n];
            catv[tid] = __ldcv(&g_ctxT[tid * 32 + n]);   // bypass stale L1 (read during lstm0 staging)
            __syncthreads();

            // q[j] = Wq[j,:] . h2 + bq[j]  (warp per j, coalesced float4 reads)
#pragma unroll 4
            for (int pass = 0; pass < 32; ++pass) {
                int j = pass * 8 + w;
                const float4* wr = (const float4*)(Wq + (size_t)j * HID) + lane * 2;
                float4 wa = wr[0], wb = wr[1];
                const float4* hv = (const float4*)(h2s) + lane * 2;
                float4 ha = hv[0], hb = hv[1];
                float a = wa.x * ha.x + wa.y * ha.y + wa.z * ha.z + wa.w * ha.w
                        + wb.x * hb.x + wb.y * hb.y + wb.z * hb.z + wb.w * hb.w;
#pragma unroll
                for (int off = 16; off > 0; off >>= 1) a += __shfl_down_sync(0xffffffffu, a, off);
                if (lane == 0) catv[HID + j] = a + bq[j];
            }
            __syncthreads();

            // hid[j] = Wo1[j,:] . catv + bo1[j]  (warp per j, 512-wide)
#pragma unroll 4
            for (int pass = 0; pass < 32; ++pass) {
                int j = pass * 8 + w;
                const float4* wr = (const float4*)(Wo1 + (size_t)j * (2 * HID)) + lane * 4;
                const float4* cv = (const float4*)(catv) + lane * 4;
                float a = 0.f;
#pragma unroll
                for (int u = 0; u < 4; u++) {
                    float4 wv = wr[u], xv = cv[u];
                    a += wv.x * xv.x + wv.y * xv.y + wv.z * xv.z + wv.w * xv.w;
                }
#pragma unroll
                for (int off = 16; off > 0; off >>= 1) a += __shfl_down_sync(0xffffffffu, a, off);
                if (lane == 0) hidv[j] = a + bo1[j];
            }
            __syncthreads();

            // logits = emb @ hid + bo2 (tied), warp per vocab row
            for (int v = w; v < VO; v += 8) {
                const float* er = emb + (size_t)v * HID;
                float a = 0.f;
#pragma unroll
                for (int h = lane; h < HID; h += 32) a += er[h] * hidv[h];
#pragma unroll
                for (int off = 16; off > 0; off >>= 1) a += __shfl_down_sync(0xffffffffu, a, off);
                if (lane == 0) out[(size_t)t * NB * VO + n * VO + v] = a + bo2[v];
            }
        }
    }

    // final arrive (no wait); last arriver resets the counter for the next launch
    __syncthreads();
    if (tid == 0) {
        __threadfence();
        int old = atomicAdd(&g_sync, 1);
        if (old == bar * NBLK + NBLK - 1) { g_sync = 0; __threadfence(); }
    }
}

// ---------------- host ----------------
extern "C" void kernel_launch(void* const* d_in, const int* in_sizes, int n_in,
                              void* d_out, int out_size)
{
    const float* seqs      = (const float*)d_in[0];
    const int*   seq_lens  = (const int*)d_in[1];
    const int*   label_in  = (const int*)d_in[2];
    const float* embedding = (const float*)d_in[3];
    const float* inith     = (const float*)d_in[4];
    const float* initc     = (const float*)d_in[5];
    const float* W_ih0 = (const float*)d_in[6],  *W_hh0 = (const float*)d_in[7];
    const float* b_ih0 = (const float*)d_in[8],  *b_hh0 = (const float*)d_in[9];
    const float* W_ih1 = (const float*)d_in[10], *W_hh1 = (const float*)d_in[11];
    const float* b_ih1 = (const float*)d_in[12], *b_hh1 = (const float*)d_in[13];
    const float* W_ih2 = (const float*)d_in[14], *W_hh2 = (const float*)d_in[15];
    const float* b_ih2 = (const float*)d_in[16], *b_hh2 = (const float*)d_in[17];
    const float* Wq  = (const float*)d_in[18], *bq  = (const float*)d_in[19];
    const float* Wk  = (const float*)d_in[20], *bk  = (const float*)d_in[21];
    const float* Wv  = (const float*)d_in[22], *bv  = (const float*)d_in[23];
    const float* Wo1 = (const float*)d_in[24], *bo1 = (const float*)d_in[25];
    const float* bo2 = (const float*)d_in[26];
    float* out = (float*)d_out;

    const int SMEMB = SMF * (int)sizeof(float);   // 125952 B
    cudaFuncSetAttribute(step_kernel, cudaFuncAttributeMaxDynamicSharedMemorySize, SMEMB);

    gemm1_kernel<<<dim3(8, 1024), 256>>>(seqs, Wk, bk, Wv, bv);
    wqt_kernel<<<dim3(8, 8), dim3(32, 8)>>>(Wq);
    gemm2_kernel<<<dim3(4, 1024), 256>>>();
    sb_kernel<<<256, 256>>>(bq);
    init_kernel<<<32, 256>>>(inith, initc);

    // initial ctx from initial h2 (initmode: scores+ctx only)
    step_kernel<<<NBLK, 256, SMEMB>>>(W_ih0, W_hh0, b_ih0, b_hh0,
                                      W_ih1, W_hh1, b_ih1, b_hh1,
                                      W_ih2, W_hh2, b_ih2, b_hh2,
                                      label_in, embedding, seq_lens,
                                      Wq, bq, Wo1, bo1, bo2, out, -1, 0, 1);

    for (int t = 0; t < TS; ++t) {
        step_kernel<<<NBLK, 256, SMEMB>>>(W_ih0, W_hh0, b_ih0, b_hh0,
                                          W_ih1, W_hh1, b_ih1, b_hh1,
                                          W_ih2, W_hh2, b_ih2, b_hh2,
                                          label_in, embedding, seq_lens,
                                          Wq, bq, Wo1, bo1, bo2, out, t, t & 1, 0);
    }
}